// round 10
// baseline (speedup 1.0000x reference)
#include <cuda_runtime.h>
#include <cuda_fp16.h>

#define N_NODES 4096
#define N_CHILD 16384
#define DEGREE  64
#define BATCH   128

// Scratch: E_T[c][b] = exp(child_ll[b][c]) in fp16; 256B rows.
__device__ __align__(256) __half g_Eh[(size_t)N_CHILD * BATCH];

// ---------------------------------------------------------------------------
// Kernel 1: exp + transpose + fp16 convert for ONE batch half (64 batches).
// child_ll [B=128, C=16384] f32 -> g_Eh[c][h*64 .. h*64+64)
// ---------------------------------------------------------------------------
__global__ void __launch_bounds__(256) exp_half_kernel(
    const float* __restrict__ child_ll, const int h) {
    __shared__ float tile[64][65];
    const int c0 = blockIdx.x * 64;
    const int b0 = h * 64;

    const int q  = threadIdx.x & 15;   // float4 index along c
    const int r0 = threadIdx.x >> 4;   // row (b) 0..15
#pragma unroll
    for (int rr = 0; rr < 64; rr += 16) {
        const int r = r0 + rr;
        const float4 v = __ldcg(reinterpret_cast<const float4*>(
            &child_ll[(size_t)(b0 + r) * N_CHILD + c0 + q * 4]));
        tile[q * 4 + 0][r] = v.x;
        tile[q * 4 + 1][r] = v.y;
        tile[q * 4 + 2][r] = v.z;
        tile[q * 4 + 3][r] = v.w;
    }
    __syncthreads();

    const int c = threadIdx.x >> 2;    // 0..63
    const int s = threadIdx.x & 3;     // 0..3
#pragma unroll
    for (int hh = 0; hh < 2; hh++) {
        const int b = s * 8 + hh * 32; // 0..63 within the half
        __half2 hv[4];
#pragma unroll
        for (int j = 0; j < 4; j++) {
            const float f0 = __expf(tile[c][b + 2 * j]);
            const float f1 = __expf(tile[c][b + 2 * j + 1]);
            hv[j] = __floats2half2_rn(f0, f1);
        }
        __stcg(reinterpret_cast<uint4*>(
                   &g_Eh[(size_t)(c0 + c) * BATCH + b0 + b]),
               *reinterpret_cast<const uint4*>(hv));
    }
}

// ---------------------------------------------------------------------------
// Kernel 2: gather-reduce for ONE batch half. One warp per node; 8 nodes per
// 256-thr block; grid=512, bounds(256,4) => single wave.
// Lane = side(0..3) * 8 + g(0..7): side strides edges 4-way, g picks 16B of
// the 128B half-row (8 batches). 16 LDG.128 per lane, HFMA2 groups drained
// to fp32 every 8 edges (R5-proven precision). shfl merges sides.
// ---------------------------------------------------------------------------
__global__ void __launch_bounds__(256, 4) sum_half_kernel(
    const float* __restrict__ log_w, const int* __restrict__ cols,
    float* __restrict__ out, const int h) {
    const int tid   = threadIdx.x;
    const int wid   = tid >> 5;            // node-in-block 0..7
    const int lane  = tid & 31;
    const int node0 = blockIdx.x * 8;
    const int node  = node0 + wid;
    const int base  = node * DEGREE;

    __shared__ uint2 s_wo[8][64];          // .x = half2(w,w) bits, .y = c*256B
    __shared__ float s_o[64][9];           // [batch-in-half][node-in-block]

    // Fused weight normalization (warp shuffle reduction over 64 edges).
    {
        const float w0 = __expf(log_w[base + lane]);
        const float w1 = __expf(log_w[base + 32 + lane]);
        float ssum = w0 + w1;
#pragma unroll
        for (int o = 16; o; o >>= 1)
            ssum += __shfl_xor_sync(0xffffffffu, ssum, o);
        const float inv = 1.0f / ssum;
        __half2 a = __float2half2_rn(w0 * inv);
        __half2 b = __float2half2_rn(w1 * inv);
        s_wo[wid][lane] =
            make_uint2(*reinterpret_cast<unsigned*>(&a),
                       (unsigned)cols[base + lane] * 256u);
        s_wo[wid][lane + 32] =
            make_uint2(*reinterpret_cast<unsigned*>(&b),
                       (unsigned)cols[base + 32 + lane] * 256u);
    }
    __syncwarp();

    const int side = lane >> 3;            // 0..3: edge stride class
    const int g    = lane & 7;             // 0..7: 16B chunk of half-row
    const char* Eb = reinterpret_cast<const char*>(g_Eh) + h * 128 + g * 16;

    float fa[8] = {0.f, 0.f, 0.f, 0.f, 0.f, 0.f, 0.f, 0.f};

#pragma unroll
    for (int jj = 0; jj < 2; jj++) {
        __half2 hacc[4];
#pragma unroll
        for (int k = 0; k < 4; k++) hacc[k] = __float2half2_rn(0.f);
#pragma unroll
        for (int j8 = 0; j8 < 8; j8++) {
            const int e = (jj * 8 + j8) * 4 + side;
            const uint2 wo = s_wo[wid][e];
            const __half2 w2 = *reinterpret_cast<const __half2*>(&wo.x);
            const uint4 p = __ldcg(reinterpret_cast<const uint4*>(Eb + wo.y));
            hacc[0] = __hfma2(w2, *reinterpret_cast<const __half2*>(&p.x), hacc[0]);
            hacc[1] = __hfma2(w2, *reinterpret_cast<const __half2*>(&p.y), hacc[1]);
            hacc[2] = __hfma2(w2, *reinterpret_cast<const __half2*>(&p.z), hacc[2]);
            hacc[3] = __hfma2(w2, *reinterpret_cast<const __half2*>(&p.w), hacc[3]);
        }
#pragma unroll
        for (int k = 0; k < 4; k++) {
            const float2 f = __half22float2(hacc[k]);
            fa[2 * k]     += f.x;
            fa[2 * k + 1] += f.y;
        }
    }

    // Merge the 4 edge-stride classes (sides) within the warp.
#pragma unroll
    for (int k = 0; k < 8; k++) {
        fa[k] += __shfl_xor_sync(0xffffffffu, fa[k], 8);
        fa[k] += __shfl_xor_sync(0xffffffffu, fa[k], 16);
    }
    if (lane < 8) {
#pragma unroll
        for (int k = 0; k < 8; k++)
            s_o[g * 8 + k][wid] = __logf(fa[k]);
    }
    __syncthreads();

    // Coalesced output: 8 adjacent nodes -> 32B per batch row.
    if (tid < 128) {
        const int b = tid >> 1;            // batch within half
        const int q = (tid & 1) * 4;       // node quad
        const float4 v = make_float4(s_o[b][q + 0], s_o[b][q + 1],
                                     s_o[b][q + 2], s_o[b][q + 3]);
        *reinterpret_cast<float4*>(
            &out[(size_t)(h * 64 + b) * N_NODES + node0 + q]) = v;
    }
}

// ---------------------------------------------------------------------------
// Launch graph:
//   exp0 ──► sum0 ─────────────► sum1
//     └─ev0─► exp1 (stream s2) ─ev1─┘
// exp1 (writes E bytes [128,256) of each row) overlaps sum0 (reads [0,128)).
// Stream/events are host handles created once on the first (non-capturing)
// call; only record/wait ops are captured into the graph.
// ---------------------------------------------------------------------------
extern "C" void kernel_launch(void* const* d_in, const int* in_sizes, int n_in,
                              void* d_out, int out_size) {
    const float* child_ll = (const float*)d_in[0];  // [128, 16384] f32
    const float* log_w    = (const float*)d_in[1];  // [262144] f32
    // d_in[2] = rows: structurally repeat(arange(4096), 64) — unused
    const int*   cols     = (const int*)d_in[3];    // [262144] i32
    float*       out      = (float*)d_out;          // [128, 4096] f32

    static cudaStream_t s2  = nullptr;
    static cudaEvent_t  ev0 = nullptr;
    static cudaEvent_t  ev1 = nullptr;
    if (s2 == nullptr) {
        cudaStreamCreateWithFlags(&s2, cudaStreamNonBlocking);
        cudaEventCreateWithFlags(&ev0, cudaEventDisableTiming);
        cudaEventCreateWithFlags(&ev1, cudaEventDisableTiming);
    }

    const dim3 tg(N_CHILD / 64, 1);

    exp_half_kernel<<<tg, 256>>>(child_ll, 0);
    cudaEventRecord(ev0, 0);
    cudaStreamWaitEvent(s2, ev0, 0);
    exp_half_kernel<<<tg, 256, 0, s2>>>(child_ll, 1);
    cudaEventRecord(ev1, s2);

    sum_half_kernel<<<N_NODES / 8, 256>>>(log_w, cols, out, 0);
    cudaStreamWaitEvent(0, ev1, 0);
    sum_half_kernel<<<N_NODES / 8, 256>>>(log_w, cols, out, 1);
}

// round 11
// speedup vs baseline: 1.0657x; 1.0657x over previous
#include <cuda_runtime.h>
#include <cuda_fp16.h>

#define N_NODES 4096
#define N_CHILD 16384
#define DEGREE  64
#define BATCH   128
#define GRID    512

// Scratch: E_T[c][b] = exp(child_ll[b][c]) in fp16 (4 MB, L2-resident)
__device__ __align__(256) __half g_Eh[(size_t)N_CHILD * BATCH];
// Grid barrier: monotonic arrival counter (never reset; target derived per
// launch from old/GRID — launches are stream-serialized).
__device__ unsigned g_bar = 0;

// ---------------------------------------------------------------------------
// Fused kernel. grid=512 x 256thr, 4 blocks/SM => 592 resident slots >= 512:
// every block co-resident, so the global spin barrier cannot deadlock.
//   prologue: per-node weight normalization (hidden under phase A)
//   phase A : exp + transpose + fp16 for one 64c x 64b tile  (R5 body)
//   barrier : threadfence + atomic arrive + tid0 spin
//   phase B : gather-reduce 8 nodes/block, fp32 FMA (R4 body, 10.3us proven)
// ---------------------------------------------------------------------------
__global__ void __launch_bounds__(256, 4) fused_kernel(
    const float* __restrict__ child_ll, const float* __restrict__ log_w,
    const int* __restrict__ cols, float* __restrict__ out) {
    __shared__ float tile[64][65];      // phase A transpose buffer
    __shared__ uint2 s_wo[8][64];       // .x = fp32 w bits, .y = col*BATCH
    __shared__ float s_o[128][9];       // phase B staged output

    const int tid  = threadIdx.x;
    const int wid  = tid >> 5;          // 0..7 (node-in-block for phase B)
    const int lane = tid & 31;

    // ---- Sum prologue: normalized weights for this block's 8 nodes -------
    const int node0 = blockIdx.x * 8;
    const int base  = (node0 + wid) * DEGREE;
    {
        const float w0 = __expf(log_w[base + lane]);
        const float w1 = __expf(log_w[base + 32 + lane]);
        float ssum = w0 + w1;
#pragma unroll
        for (int o = 16; o; o >>= 1)
            ssum += __shfl_xor_sync(0xffffffffu, ssum, o);
        const float inv = 1.0f / ssum;
        s_wo[wid][lane] =
            make_uint2(__float_as_uint(w0 * inv),
                       (unsigned)cols[base + lane] * BATCH);
        s_wo[wid][lane + 32] =
            make_uint2(__float_as_uint(w1 * inv),
                       (unsigned)cols[base + 32 + lane] * BATCH);
    }

    // ---- Phase A: exp-transpose one 64c x 64b tile ------------------------
    const int c0 = (blockIdx.x & 255) * 64;
    const int b0 = (blockIdx.x >> 8) * 64;
    {
        const int q  = tid & 15;        // float4 index along c
        const int r0 = tid >> 4;        // row (b) 0..15
#pragma unroll
        for (int rr = 0; rr < 64; rr += 16) {
            const int r = r0 + rr;
            const float4 v = __ldcg(reinterpret_cast<const float4*>(
                &child_ll[(size_t)(b0 + r) * N_CHILD + c0 + q * 4]));
            tile[q * 4 + 0][r] = v.x;
            tile[q * 4 + 1][r] = v.y;
            tile[q * 4 + 2][r] = v.z;
            tile[q * 4 + 3][r] = v.w;
        }
        __syncthreads();

        const int c = tid >> 2;         // 0..63
        const int s = tid & 3;          // 0..3
#pragma unroll
        for (int h = 0; h < 2; h++) {
            const int b = s * 8 + h * 32;
            __half2 hv[4];
#pragma unroll
            for (int j = 0; j < 4; j++) {
                const float f0 = __expf(tile[c][b + 2 * j]);
                const float f1 = __expf(tile[c][b + 2 * j + 1]);
                hv[j] = __floats2half2_rn(f0, f1);
            }
            __stcg(reinterpret_cast<uint4*>(
                       &g_Eh[(size_t)(c0 + c) * BATCH + b0 + b]),
                   *reinterpret_cast<const uint4*>(hv));
        }
    }

    // ---- Grid barrier -----------------------------------------------------
    __threadfence();                    // publish E writes before arriving
    __syncthreads();                    // whole block done with phase A
    if (tid == 0) {
        const unsigned old    = atomicAdd(&g_bar, 1u);
        const unsigned target = (old / GRID) * GRID + GRID;
        while (atomicAdd(&g_bar, 0u) < target) __nanosleep(64);
        __threadfence();
    }
    __syncthreads();                    // release whole block into phase B

    // ---- Phase B: gather-reduce (one warp per node, fp32 FMA) -------------
    const int g    = lane & 15;         // batch-group: batches g*8..g*8+7
    const int side = lane >> 4;         // 0: even edges, 1: odd edges
    const __half* Eg = g_Eh + g * 8;

    float a0 = 0.f, a1 = 0.f, a2 = 0.f, a3 = 0.f;
    float a4 = 0.f, a5 = 0.f, a6 = 0.f, a7 = 0.f;

#pragma unroll 8
    for (int j = 0; j < 32; j++) {
        const uint2 wo = s_wo[wid][2 * j + side];
        const float w  = __uint_as_float(wo.x);
        const uint4 p  = __ldcg(reinterpret_cast<const uint4*>(Eg + wo.y));
        float2 f;
        f = __half22float2(*reinterpret_cast<const __half2*>(&p.x));
        a0 = fmaf(w, f.x, a0); a1 = fmaf(w, f.y, a1);
        f = __half22float2(*reinterpret_cast<const __half2*>(&p.y));
        a2 = fmaf(w, f.x, a2); a3 = fmaf(w, f.y, a3);
        f = __half22float2(*reinterpret_cast<const __half2*>(&p.z));
        a4 = fmaf(w, f.x, a4); a5 = fmaf(w, f.y, a5);
        f = __half22float2(*reinterpret_cast<const __half2*>(&p.w));
        a6 = fmaf(w, f.x, a6); a7 = fmaf(w, f.y, a7);
    }

    // Merge even/odd sides; side-0 lanes finish with log.
    a0 += __shfl_xor_sync(0xffffffffu, a0, 16);
    a1 += __shfl_xor_sync(0xffffffffu, a1, 16);
    a2 += __shfl_xor_sync(0xffffffffu, a2, 16);
    a3 += __shfl_xor_sync(0xffffffffu, a3, 16);
    a4 += __shfl_xor_sync(0xffffffffu, a4, 16);
    a5 += __shfl_xor_sync(0xffffffffu, a5, 16);
    a6 += __shfl_xor_sync(0xffffffffu, a6, 16);
    a7 += __shfl_xor_sync(0xffffffffu, a7, 16);
    if (side == 0) {
        s_o[g * 8 + 0][wid] = __logf(a0);
        s_o[g * 8 + 1][wid] = __logf(a1);
        s_o[g * 8 + 2][wid] = __logf(a2);
        s_o[g * 8 + 3][wid] = __logf(a3);
        s_o[g * 8 + 4][wid] = __logf(a4);
        s_o[g * 8 + 5][wid] = __logf(a5);
        s_o[g * 8 + 6][wid] = __logf(a6);
        s_o[g * 8 + 7][wid] = __logf(a7);
    }
    __syncthreads();

    // Coalesced output: 8 adjacent nodes -> full 32B sectors per batch row.
    const int bb = tid >> 1;
    const int h  = (tid & 1) * 4;
    const float4 v = make_float4(s_o[bb][h + 0], s_o[bb][h + 1],
                                 s_o[bb][h + 2], s_o[bb][h + 3]);
    *reinterpret_cast<float4*>(&out[(size_t)bb * N_NODES + node0 + h]) = v;
}

// ---------------------------------------------------------------------------
extern "C" void kernel_launch(void* const* d_in, const int* in_sizes, int n_in,
                              void* d_out, int out_size) {
    const float* child_ll = (const float*)d_in[0];  // [128, 16384] f32
    const float* log_w    = (const float*)d_in[1];  // [262144] f32
    // d_in[2] = rows: structurally repeat(arange(4096), 64) — unused
    const int*   cols     = (const int*)d_in[3];    // [262144] i32
    float*       out      = (float*)d_out;          // [128, 4096] f32

    fused_kernel<<<GRID, 256>>>(child_ll, log_w, cols, out);
}